// round 1
// baseline (speedup 1.0000x reference)
#include <cuda_runtime.h>
#include <math.h>

// Scratch: per-row (U) and per-col (V) rank-11 feature vectors.
// Max 8192 rows/cols supported; actual problem is 2048.
#define KMAX 8192
__device__ float g_U[KMAX * 11];        // [N][11] row-major
__device__ float g_V[11 * KMAX];        // [11][M] component-major (float4-friendly)

__device__ __forceinline__ void kent_frame(const float* __restrict__ p,
                                           float g1[3], float g2[3], float g3[3],
                                           float& kappa, float& beta) {
    float eta = p[0], alpha = p[1], psi = p[2];
    kappa = p[3]; beta = p[4];
    float sa, ca, se, ce, sp, cp;
    sincosf(alpha, &sa, &ca);
    sincosf(eta,   &se, &ce);
    sincosf(psi,   &sp, &cp);
    g1[0] = ca;        g1[1] = sa * ce;                 g1[2] = sa * se;
    g2[0] = -cp * sa;  g2[1] = cp * ca * ce - sp * se;  g2[2] = cp * ca * se + sp * ce;
    g3[0] = sp * sa;   g3[1] = -sp * ca * ce - cp * se; g3[2] = -sp * ca * se + cp * ce;
}

__global__ void kent_precompute(const float* __restrict__ pred,
                                const float* __restrict__ targ,
                                int N, int M) {
    const float TWO_PI = 6.2831853071795864769f;
    const float EIGHT_PI = 25.132741228718345908f;
    const float EPS = 1e-6f;
    int i = blockIdx.x * blockDim.x + threadIdx.x;

    if (i < N) {
        float g1[3], g2[3], g3[3], kappa, beta;
        kent_frame(pred + (size_t)i * 5, g1, g2, g3, kappa, beta);

        float km = kappa - 2.f * beta, kp = kappa + 2.f * beta;
        float lkm = logf(km), lkp = logf(kp);

        // c = log_approximate_c
        float c = logf(TWO_PI) + kappa - 0.5f * logf(km * kp + EPS);
        // c_k = log_del_kappa
        float ck = logf(-TWO_PI * (4.f * beta * beta + kappa - kappa * kappa)) + kappa
                 - (1.5f * lkm + 1.5f * lkp + EPS);
        // c_kk = log_del_2_kappa
        float k2 = kappa * kappa, b2 = beta * beta;
        float poly = k2 * k2 - 2.f * kappa * k2 + (2.f - 8.f * b2) * k2
                   + 8.f * b2 * kappa + 16.f * b2 * b2 + 4.f * b2;
        float ckk = logf(TWO_PI * poly) + kappa - (2.5f * lkm + 2.5f * lkp + EPS);
        // c_beta = log_del_beta
        float cbeta = logf(EIGHT_PI * kappa) + logf(beta)
                    - (1.5f * lkm + 1.5f * lkp + EPS);

        float l1  = expf(ck  - c);
        float ekk = expf(ckk - c);
        float eb  = expf(cbeta - c);
        float l2 = 0.5f * (1.f - ekk + eb);
        float l3 = 0.5f * (1.f - ekk - eb);

        // ExxT_a = Q diag(l) Q^T, symmetric: store 00,11,22,01,02,12
        float E00 = l1*g1[0]*g1[0] + l2*g2[0]*g2[0] + l3*g3[0]*g3[0];
        float E11 = l1*g1[1]*g1[1] + l2*g2[1]*g2[1] + l3*g3[1]*g3[1];
        float E22 = l1*g1[2]*g1[2] + l2*g2[2]*g2[2] + l3*g3[2]*g3[2];
        float E01 = l1*g1[0]*g1[1] + l2*g2[0]*g2[1] + l3*g3[0]*g3[1];
        float E02 = l1*g1[0]*g1[2] + l2*g2[0]*g2[2] + l3*g3[0]*g3[2];
        float E12 = l1*g1[1]*g1[2] + l2*g2[1]*g2[2] + l3*g3[1]*g3[2];

        float Ex0 = l1 * g1[0], Ex1 = l1 * g1[1], Ex2 = l1 * g1[2];

        // quadratic forms with gamma_a2 / gamma_a3
        float qa2 = E00*g2[0]*g2[0] + E11*g2[1]*g2[1] + E22*g2[2]*g2[2]
                  + 2.f*(E01*g2[0]*g2[1] + E02*g2[0]*g2[2] + E12*g2[1]*g2[2]);
        float qa3 = E00*g3[0]*g3[0] + E11*g3[1]*g3[1] + E22*g3[2]*g3[2]
                  + 2.f*(E01*g3[0]*g3[1] + E02*g3[0]*g3[2] + E12*g3[1]*g3[2]);

        float kdot = kappa * (g1[0]*Ex0 + g1[1]*Ex1 + g1[2]*Ex2);
        float S = -c + kdot + beta * (qa2 - qa3);

        float* U = g_U + (size_t)i * 11;
        U[0]  = S;
        U[1]  = 1.f;
        U[2]  = Ex0;  U[3] = Ex1;  U[4] = Ex2;
        U[5]  = E00;  U[6] = E11;  U[7] = E22;
        U[8]  = 2.f * E01;  U[9] = 2.f * E02;  U[10] = 2.f * E12;
    }

    if (i < M) {
        float g1[3], g2[3], g3[3], kappa, beta;
        kent_frame(targ + (size_t)i * 5, g1, g2, g3, kappa, beta);

        float km = kappa - 2.f * beta, kp = kappa + 2.f * beta;
        float cb = logf(TWO_PI) + kappa - 0.5f * logf(km * kp + EPS);

        g_V[0*(size_t)M + i] = 1.f;
        g_V[1*(size_t)M + i] = cb;
        g_V[2*(size_t)M + i] = -kappa * g1[0];
        g_V[3*(size_t)M + i] = -kappa * g1[1];
        g_V[4*(size_t)M + i] = -kappa * g1[2];
        // beta_b * (g3 g3^T - g2 g2^T): diag pairs with E_ii, off pairs with 2*E_ij
        g_V[5*(size_t)M + i] = beta * (g3[0]*g3[0] - g2[0]*g2[0]);
        g_V[6*(size_t)M + i] = beta * (g3[1]*g3[1] - g2[1]*g2[1]);
        g_V[7*(size_t)M + i] = beta * (g3[2]*g3[2] - g2[2]*g2[2]);
        g_V[8*(size_t)M + i] = beta * (g3[0]*g3[1] - g2[0]*g2[1]);
        g_V[9*(size_t)M + i] = beta * (g3[0]*g3[2] - g2[0]*g2[2]);
        g_V[10*(size_t)M + i] = beta * (g3[1]*g3[2] - g2[1]*g2[2]);
    }
}

// Rank-11 "GEMM": out[n][m] = U[n] . V[:,m]
// Block: 128 threads, each owns 4 consecutive cols (float4), 16 rows per block.
#define KLD_THREADS 128
#define KLD_ROWS    16

__global__ void __launch_bounds__(KLD_THREADS)
kld_main(float* __restrict__ out, int N, int M) {
    int col  = (blockIdx.x * KLD_THREADS + threadIdx.x) * 4;
    int row0 = blockIdx.y * KLD_ROWS;
    int nrows = N - row0;
    if (nrows > KLD_ROWS) nrows = KLD_ROWS;

    __shared__ float sU[KLD_ROWS * 11];
    for (int t = threadIdx.x; t < nrows * 11; t += KLD_THREADS)
        sU[t] = g_U[(size_t)row0 * 11 + t];
    __syncthreads();

    if (col >= M) return;
    bool vec = ((M & 3) == 0) && (col + 4 <= M);

    float4 v[11];
    if (vec) {
#pragma unroll
        for (int k = 0; k < 11; k++)
            v[k] = *reinterpret_cast<const float4*>(&g_V[(size_t)k * M + col]);
    } else {
#pragma unroll
        for (int k = 0; k < 11; k++) {
            const float* base = &g_V[(size_t)k * M];
            v[k].x = (col + 0 < M) ? base[col + 0] : 0.f;
            v[k].y = (col + 1 < M) ? base[col + 1] : 0.f;
            v[k].z = (col + 2 < M) ? base[col + 2] : 0.f;
            v[k].w = (col + 3 < M) ? base[col + 3] : 0.f;
        }
    }

    for (int r = 0; r < nrows; r++) {
        const float* u = sU + r * 11;   // broadcast read across the block
        float u0 = u[0];
        float4 acc;
        acc.x = u0 * v[0].x;
        acc.y = u0 * v[0].y;
        acc.z = u0 * v[0].z;
        acc.w = u0 * v[0].w;
#pragma unroll
        for (int k = 1; k < 11; k++) {
            float uk = u[k];
            acc.x = fmaf(uk, v[k].x, acc.x);
            acc.y = fmaf(uk, v[k].y, acc.y);
            acc.z = fmaf(uk, v[k].z, acc.z);
            acc.w = fmaf(uk, v[k].w, acc.w);
        }
        size_t off = (size_t)(row0 + r) * M + col;
        if (vec) {
            *reinterpret_cast<float4*>(out + off) = acc;
        } else {
            if (col + 0 < M) out[off + 0] = acc.x;
            if (col + 1 < M) out[off + 1] = acc.y;
            if (col + 2 < M) out[off + 2] = acc.z;
            if (col + 3 < M) out[off + 3] = acc.w;
        }
    }
}

extern "C" void kernel_launch(void* const* d_in, const int* in_sizes, int n_in,
                              void* d_out, int out_size) {
    const float* pred = (const float*)d_in[0];
    const float* targ = (const float*)d_in[1];
    float* out = (float*)d_out;
    int N = in_sizes[0] / 5;
    int M = in_sizes[1] / 5;

    int mx = (N > M) ? N : M;
    kent_precompute<<<(mx + 255) / 256, 256>>>(pred, targ, N, M);

    dim3 grid((M + KLD_THREADS * 4 - 1) / (KLD_THREADS * 4),
              (N + KLD_ROWS - 1) / KLD_ROWS);
    kld_main<<<grid, KLD_THREADS>>>(out, N, M);
}

// round 2
// speedup vs baseline: 1.2119x; 1.2119x over previous
#include <cuda_runtime.h>
#include <math.h>

#define KMAX 8192
__device__ float g_U[KMAX * 11];        // [N][11] row-major
__device__ float g_V[11 * KMAX];        // [11][M] component-major

// ---------------- packed f32x2 helpers (ptxas won't auto-fuse; PTX only) ----
__device__ __forceinline__ unsigned long long fma2(unsigned long long a,
                                                   unsigned long long b,
                                                   unsigned long long c) {
    unsigned long long d;
    asm("fma.rn.f32x2 %0, %1, %2, %3;" : "=l"(d) : "l"(a), "l"(b), "l"(c));
    return d;
}
__device__ __forceinline__ unsigned long long mul2(unsigned long long a,
                                                   unsigned long long b) {
    unsigned long long d;
    asm("mul.rn.f32x2 %0, %1, %2;" : "=l"(d) : "l"(a), "l"(b));
    return d;
}
union F4U { float4 f; struct { unsigned long long lo, hi; } u; };

// ---------------- per-row / per-col feature precompute ----------------------
__device__ __forceinline__ void kent_frame(const float* __restrict__ p,
                                           float g1[3], float g2[3], float g3[3],
                                           float& kappa, float& beta) {
    float eta = p[0], alpha = p[1], psi = p[2];
    kappa = p[3]; beta = p[4];
    float sa, ca, se, ce, sp, cp;
    sincosf(alpha, &sa, &ca);
    sincosf(eta,   &se, &ce);
    sincosf(psi,   &sp, &cp);
    g1[0] = ca;        g1[1] = sa * ce;                 g1[2] = sa * se;
    g2[0] = -cp * sa;  g2[1] = cp * ca * ce - sp * se;  g2[2] = cp * ca * se + sp * ce;
    g3[0] = sp * sa;   g3[1] = -sp * ca * ce - cp * se; g3[2] = -sp * ca * se + cp * ce;
}

__global__ void kent_precompute(const float* __restrict__ pred,
                                const float* __restrict__ targ,
                                int N, int M) {
    const float TWO_PI = 6.2831853071795864769f;
    const float EIGHT_PI = 25.132741228718345908f;
    const float EPS = 1e-6f;
    int i = blockIdx.x * blockDim.x + threadIdx.x;

    if (i < N) {
        float g1[3], g2[3], g3[3], kappa, beta;
        kent_frame(pred + (size_t)i * 5, g1, g2, g3, kappa, beta);

        float km = kappa - 2.f * beta, kp = kappa + 2.f * beta;
        float lkm = logf(km), lkp = logf(kp);

        float c = logf(TWO_PI) + kappa - 0.5f * logf(km * kp + EPS);
        float ck = logf(-TWO_PI * (4.f * beta * beta + kappa - kappa * kappa)) + kappa
                 - (1.5f * lkm + 1.5f * lkp + EPS);
        float k2 = kappa * kappa, b2 = beta * beta;
        float poly = k2 * k2 - 2.f * kappa * k2 + (2.f - 8.f * b2) * k2
                   + 8.f * b2 * kappa + 16.f * b2 * b2 + 4.f * b2;
        float ckk = logf(TWO_PI * poly) + kappa - (2.5f * lkm + 2.5f * lkp + EPS);
        float cbeta = logf(EIGHT_PI * kappa) + logf(beta)
                    - (1.5f * lkm + 1.5f * lkp + EPS);

        float l1  = expf(ck  - c);
        float ekk = expf(ckk - c);
        float eb  = expf(cbeta - c);
        float l2 = 0.5f * (1.f - ekk + eb);
        float l3 = 0.5f * (1.f - ekk - eb);

        float E00 = l1*g1[0]*g1[0] + l2*g2[0]*g2[0] + l3*g3[0]*g3[0];
        float E11 = l1*g1[1]*g1[1] + l2*g2[1]*g2[1] + l3*g3[1]*g3[1];
        float E22 = l1*g1[2]*g1[2] + l2*g2[2]*g2[2] + l3*g3[2]*g3[2];
        float E01 = l1*g1[0]*g1[1] + l2*g2[0]*g2[1] + l3*g3[0]*g3[1];
        float E02 = l1*g1[0]*g1[2] + l2*g2[0]*g2[2] + l3*g3[0]*g3[2];
        float E12 = l1*g1[1]*g1[2] + l2*g2[1]*g2[2] + l3*g3[1]*g3[2];

        float Ex0 = l1 * g1[0], Ex1 = l1 * g1[1], Ex2 = l1 * g1[2];

        float qa2 = E00*g2[0]*g2[0] + E11*g2[1]*g2[1] + E22*g2[2]*g2[2]
                  + 2.f*(E01*g2[0]*g2[1] + E02*g2[0]*g2[2] + E12*g2[1]*g2[2]);
        float qa3 = E00*g3[0]*g3[0] + E11*g3[1]*g3[1] + E22*g3[2]*g3[2]
                  + 2.f*(E01*g3[0]*g3[1] + E02*g3[0]*g3[2] + E12*g3[1]*g3[2]);

        float kdot = kappa * (g1[0]*Ex0 + g1[1]*Ex1 + g1[2]*Ex2);
        float S = -c + kdot + beta * (qa2 - qa3);

        float* U = g_U + (size_t)i * 11;
        U[0]  = S;
        U[1]  = 1.f;
        U[2]  = Ex0;  U[3] = Ex1;  U[4] = Ex2;
        U[5]  = E00;  U[6] = E11;  U[7] = E22;
        U[8]  = 2.f * E01;  U[9] = 2.f * E02;  U[10] = 2.f * E12;
    }

    if (i < M) {
        float g1[3], g2[3], g3[3], kappa, beta;
        kent_frame(targ + (size_t)i * 5, g1, g2, g3, kappa, beta);

        float km = kappa - 2.f * beta, kp = kappa + 2.f * beta;
        float cb = logf(TWO_PI) + kappa - 0.5f * logf(km * kp + EPS);

        g_V[0*(size_t)M + i] = 1.f;
        g_V[1*(size_t)M + i] = cb;
        g_V[2*(size_t)M + i] = -kappa * g1[0];
        g_V[3*(size_t)M + i] = -kappa * g1[1];
        g_V[4*(size_t)M + i] = -kappa * g1[2];
        g_V[5*(size_t)M + i] = beta * (g3[0]*g3[0] - g2[0]*g2[0]);
        g_V[6*(size_t)M + i] = beta * (g3[1]*g3[1] - g2[1]*g2[1]);
        g_V[7*(size_t)M + i] = beta * (g3[2]*g3[2] - g2[2]*g2[2]);
        g_V[8*(size_t)M + i] = beta * (g3[0]*g3[1] - g2[0]*g2[1]);
        g_V[9*(size_t)M + i] = beta * (g3[0]*g3[2] - g2[0]*g2[2]);
        g_V[10*(size_t)M + i] = beta * (g3[1]*g3[2] - g2[1]*g2[2]);
    }
}

// ---------------- rank-11 outer-product kernel ------------------------------
// 128 threads, each owns 4 consecutive cols (float4), 8 rows per block.
// U rows are held in shared memory DUPLICATED per component ({u,u} pairs) so
// one LDS.128 delivers two FFMA2-ready broadcast operands.
#define KLD_THREADS 128
#define KLD_ROWS    8

__global__ void __launch_bounds__(KLD_THREADS)
kld_main(float* __restrict__ out, int N, int M) {
    int col  = (blockIdx.x * KLD_THREADS + threadIdx.x) * 4;
    int row0 = blockIdx.y * KLD_ROWS;
    int nrows = N - row0;
    if (nrows > KLD_ROWS) nrows = KLD_ROWS;

    __shared__ float2 sU[KLD_ROWS][12];   // [row][k] = {u_k, u_k}; k=11 pad
    for (int t = threadIdx.x; t < nrows * 11; t += KLD_THREADS) {
        int r = t / 11, k = t - r * 11;
        float v = g_U[(size_t)(row0 + r) * 11 + k];
        sU[r][k] = make_float2(v, v);
    }
    if (threadIdx.x < KLD_ROWS) sU[threadIdx.x][11] = make_float2(0.f, 0.f);
    __syncthreads();

    if (col >= M) return;
    bool vec = ((M & 3) == 0) && (col + 4 <= M);

    if (vec) {
        unsigned long long vlo[11], vhi[11];
#pragma unroll
        for (int k = 0; k < 11; k++) {
            F4U t;
            t.f = *reinterpret_cast<const float4*>(&g_V[(size_t)k * M + col]);
            vlo[k] = t.u.lo; vhi[k] = t.u.hi;
        }
        for (int r = 0; r < nrows; r++) {
            const float4* uj = reinterpret_cast<const float4*>(sU[r]);
            unsigned long long alo, ahi;
            {
                F4U u; u.f = uj[0];                       // {u0,u0,u1,u1}
                alo = mul2(u.u.lo, vlo[0]);  ahi = mul2(u.u.lo, vhi[0]);
                alo = fma2(u.u.hi, vlo[1], alo); ahi = fma2(u.u.hi, vhi[1], ahi);
            }
#pragma unroll
            for (int j = 1; j < 5; j++) {
                F4U u; u.f = uj[j];                       // {u2j,u2j,u2j+1,u2j+1}
                alo = fma2(u.u.lo, vlo[2*j],   alo); ahi = fma2(u.u.lo, vhi[2*j],   ahi);
                alo = fma2(u.u.hi, vlo[2*j+1], alo); ahi = fma2(u.u.hi, vhi[2*j+1], ahi);
            }
            {
                F4U u; u.f = uj[5];                       // {u10,u10,pad,pad}
                alo = fma2(u.u.lo, vlo[10], alo); ahi = fma2(u.u.lo, vhi[10], ahi);
            }
            F4U res; res.u.lo = alo; res.u.hi = ahi;
            *reinterpret_cast<float4*>(out + (size_t)(row0 + r) * M + col) = res.f;
        }
    } else {
        // scalar tail fallback
        float v[11];
#pragma unroll
        for (int k = 0; k < 11; k++) v[k] = 0.f;
        int ncols = M - col; if (ncols > 4) ncols = 4;
        for (int cc = 0; cc < ncols; cc++) {
#pragma unroll
            for (int k = 0; k < 11; k++) v[k] = g_V[(size_t)k * M + col + cc];
            for (int r = 0; r < nrows; r++) {
                float acc = sU[r][0].x * v[0];
#pragma unroll
                for (int k = 1; k < 11; k++) acc = fmaf(sU[r][k].x, v[k], acc);
                out[(size_t)(row0 + r) * M + col + cc] = acc;
            }
        }
    }
}

extern "C" void kernel_launch(void* const* d_in, const int* in_sizes, int n_in,
                              void* d_out, int out_size) {
    const float* pred = (const float*)d_in[0];
    const float* targ = (const float*)d_in[1];
    float* out = (float*)d_out;
    int N = in_sizes[0] / 5;
    int M = in_sizes[1] / 5;

    int mx = (N > M) ? N : M;
    // spread latency-bound transcendental work across many SMs
    kent_precompute<<<(mx + 31) / 32, 32>>>(pred, targ, N, M);

    dim3 grid((M + KLD_THREADS * 4 - 1) / (KLD_THREADS * 4),
              (N + KLD_ROWS - 1) / KLD_ROWS);
    kld_main<<<grid, KLD_THREADS>>>(out, N, M);
}

// round 3
// speedup vs baseline: 1.2648x; 1.0436x over previous
#include <cuda_runtime.h>
#include <math.h>

// ---------------- packed f32x2 helpers (PTX-only; ptxas won't auto-fuse) ----
__device__ __forceinline__ unsigned long long fma2(unsigned long long a,
                                                   unsigned long long b,
                                                   unsigned long long c) {
    unsigned long long d;
    asm("fma.rn.f32x2 %0, %1, %2, %3;" : "=l"(d) : "l"(a), "l"(b), "l"(c));
    return d;
}
__device__ __forceinline__ unsigned long long mul2(unsigned long long a,
                                                   unsigned long long b) {
    unsigned long long d;
    asm("mul.rn.f32x2 %0, %1, %2;" : "=l"(d) : "l"(a), "l"(b));
    return d;
}
__device__ __forceinline__ unsigned long long pk2(float lo, float hi) {
    unsigned long long r;
    asm("mov.b64 %0, {%1, %2};" : "=l"(r) : "f"(lo), "f"(hi));
    return r;
}
union F4U { float4 f; struct { unsigned long long lo, hi; } u; };

// ---------------- per-row U features (accurate path, computed 4x redundant) -
__device__ __forceinline__ void compute_U(const float* __restrict__ p,
                                          float2* __restrict__ Urow) {
    const float TWO_PI = 6.2831853071795864769f;
    const float EIGHT_PI = 25.132741228718345908f;
    const float EPS = 1e-6f;

    float eta = p[0], alpha = p[1], psi = p[2];
    float kappa = p[3], beta = p[4];
    float sa, ca, se, ce, sp, cp;
    sincosf(alpha, &sa, &ca);
    sincosf(eta,   &se, &ce);
    sincosf(psi,   &sp, &cp);
    float g1[3] = { ca,       sa * ce,                  sa * se };
    float g2[3] = { -cp * sa, cp * ca * ce - sp * se,   cp * ca * se + sp * ce };
    float g3[3] = { sp * sa,  -sp * ca * ce - cp * se,  -sp * ca * se + cp * ce };

    float km = kappa - 2.f * beta, kp = kappa + 2.f * beta;
    float lkm = logf(km), lkp = logf(kp);

    float c  = logf(TWO_PI) + kappa - 0.5f * logf(km * kp + EPS);
    float ck = logf(-TWO_PI * (4.f * beta * beta + kappa - kappa * kappa)) + kappa
             - (1.5f * lkm + 1.5f * lkp + EPS);
    float k2 = kappa * kappa, b2 = beta * beta;
    float poly = k2 * k2 - 2.f * kappa * k2 + (2.f - 8.f * b2) * k2
               + 8.f * b2 * kappa + 16.f * b2 * b2 + 4.f * b2;
    float ckk = logf(TWO_PI * poly) + kappa - (2.5f * lkm + 2.5f * lkp + EPS);
    float cbeta = logf(EIGHT_PI * kappa) + logf(beta)
                - (1.5f * lkm + 1.5f * lkp + EPS);

    float l1  = expf(ck  - c);
    float ekk = expf(ckk - c);
    float eb  = expf(cbeta - c);
    float l2 = 0.5f * (1.f - ekk + eb);
    float l3 = 0.5f * (1.f - ekk - eb);

    float E00 = l1*g1[0]*g1[0] + l2*g2[0]*g2[0] + l3*g3[0]*g3[0];
    float E11 = l1*g1[1]*g1[1] + l2*g2[1]*g2[1] + l3*g3[1]*g3[1];
    float E22 = l1*g1[2]*g1[2] + l2*g2[2]*g2[2] + l3*g3[2]*g3[2];
    float E01 = l1*g1[0]*g1[1] + l2*g2[0]*g2[1] + l3*g3[0]*g3[1];
    float E02 = l1*g1[0]*g1[2] + l2*g2[0]*g2[2] + l3*g3[0]*g3[2];
    float E12 = l1*g1[1]*g1[2] + l2*g2[1]*g2[2] + l3*g3[1]*g3[2];

    float Ex0 = l1 * g1[0], Ex1 = l1 * g1[1], Ex2 = l1 * g1[2];

    float qa2 = E00*g2[0]*g2[0] + E11*g2[1]*g2[1] + E22*g2[2]*g2[2]
              + 2.f*(E01*g2[0]*g2[1] + E02*g2[0]*g2[2] + E12*g2[1]*g2[2]);
    float qa3 = E00*g3[0]*g3[0] + E11*g3[1]*g3[1] + E22*g3[2]*g3[2]
              + 2.f*(E01*g3[0]*g3[1] + E02*g3[0]*g3[2] + E12*g3[1]*g3[2]);

    float kdot = kappa * (g1[0]*Ex0 + g1[1]*Ex1 + g1[2]*Ex2);
    float S = -c + kdot + beta * (qa2 - qa3);

    float u[11] = { S, 1.f, Ex0, Ex1, Ex2, E00, E11, E22,
                    2.f*E01, 2.f*E02, 2.f*E12 };
#pragma unroll
    for (int k = 0; k < 11; k++) Urow[k] = make_float2(u[k], u[k]);
    Urow[11] = make_float2(0.f, 0.f);
}

// ---------------- per-col V features (fast intrinsics, hot path) ------------
__device__ __forceinline__ void compute_V(float eta, float alpha, float psi,
                                          float kappa, float beta,
                                          float v[11]) {
    const float LOG_TWO_PI = 1.8378770664093454836f;
    const float EPS = 1e-6f;
    float sa, ca, se, ce, sp, cp;
    __sincosf(alpha, &sa, &ca);
    __sincosf(eta,   &se, &ce);
    __sincosf(psi,   &sp, &cp);
    float g1x = ca,       g1y = sa * ce,                 g1z = sa * se;
    float g2x = -cp * sa, g2y = cp * ca * ce - sp * se,  g2z = cp * ca * se + sp * ce;
    float g3x = sp * sa,  g3y = -sp * ca * ce - cp * se, g3z = -sp * ca * se + cp * ce;

    float km = kappa - 2.f * beta, kp = kappa + 2.f * beta;
    float cb = LOG_TWO_PI + kappa - 0.5f * __logf(km * kp + EPS);

    v[0] = 1.f;
    v[1] = cb;
    v[2] = -kappa * g1x;
    v[3] = -kappa * g1y;
    v[4] = -kappa * g1z;
    v[5] = beta * (g3x*g3x - g2x*g2x);
    v[6] = beta * (g3y*g3y - g2y*g2y);
    v[7] = beta * (g3z*g3z - g2z*g2z);
    v[8] = beta * (g3x*g3y - g2x*g2y);
    v[9] = beta * (g3x*g3z - g2x*g2z);
    v[10] = beta * (g3y*g3z - g2y*g2z);
}

// ---------------- fused kernel ----------------------------------------------
// Block: 128 threads, tile = 8 rows x 512 cols. Each thread owns 4 cols.
// V recomputed in-registers from targ (5 LDG.128/thread); U computed inline
// by threads 0..7 into shared, duplicated-packed for FFMA2 broadcast.
#define KLD_THREADS 128
#define KLD_ROWS    8

__global__ void __launch_bounds__(KLD_THREADS, 7)
kld_fused(const float* __restrict__ pred, const float* __restrict__ targ,
          float* __restrict__ out, int N, int M) {
    int tid  = threadIdx.x;
    int col  = (blockIdx.x * KLD_THREADS + tid) * 4;
    int row0 = blockIdx.y * KLD_ROWS;
    int nrows = N - row0;
    if (nrows > KLD_ROWS) nrows = KLD_ROWS;

    __shared__ float2 sU[KLD_ROWS][12];

    // --- U: threads 0..nrows-1 compute one row each (4x grid.x redundancy) ---
    if (tid < nrows)
        compute_U(pred + (size_t)(row0 + tid) * 5, sU[tid]);

    // --- V: each thread, 4 cols from raw targ params --------------------------
    bool vec = ((M & 3) == 0) && (col + 4 <= M);
    unsigned long long vA[11], vB[11];   // cols {0,1} and {2,3} packed
    float vs[11];                        // scalar-path storage (first col)

    if (vec) {
        // 20 consecutive floats, 16B-aligned (col%4==0 -> 80B offset)
        float tp[20];
        const float4* src = reinterpret_cast<const float4*>(targ + (size_t)col * 5);
#pragma unroll
        for (int q = 0; q < 5; q++)
            *reinterpret_cast<float4*>(&tp[q * 4]) = src[q];

        float v0[11], v1[11];
        compute_V(tp[0],  tp[1],  tp[2],  tp[3],  tp[4],  v0);
        compute_V(tp[5],  tp[6],  tp[7],  tp[8],  tp[9],  v1);
#pragma unroll
        for (int k = 0; k < 11; k++) vA[k] = pk2(v0[k], v1[k]);
        compute_V(tp[10], tp[11], tp[12], tp[13], tp[14], v0);
        compute_V(tp[15], tp[16], tp[17], tp[18], tp[19], v1);
#pragma unroll
        for (int k = 0; k < 11; k++) vB[k] = pk2(v0[k], v1[k]);
    }

    __syncthreads();

    if (vec) {
        if (nrows == KLD_ROWS) {
#pragma unroll
            for (int r = 0; r < KLD_ROWS; r++) {
                const float4* uj = reinterpret_cast<const float4*>(sU[r]);
                unsigned long long alo, ahi;
                {
                    F4U u; u.f = uj[0];                     // {u0,u0,u1,u1}
                    alo = mul2(u.u.lo, vA[0]);  ahi = mul2(u.u.lo, vB[0]);
                    alo = fma2(u.u.hi, vA[1], alo); ahi = fma2(u.u.hi, vB[1], ahi);
                }
#pragma unroll
                for (int j = 1; j < 5; j++) {
                    F4U u; u.f = uj[j];                     // {u2j,u2j,u2j+1,u2j+1}
                    alo = fma2(u.u.lo, vA[2*j],   alo); ahi = fma2(u.u.lo, vB[2*j],   ahi);
                    alo = fma2(u.u.hi, vA[2*j+1], alo); ahi = fma2(u.u.hi, vB[2*j+1], ahi);
                }
                {
                    F4U u; u.f = uj[5];                     // {u10,u10,pad,pad}
                    alo = fma2(u.u.lo, vA[10], alo); ahi = fma2(u.u.lo, vB[10], ahi);
                }
                F4U res; res.u.lo = alo; res.u.hi = ahi;
                *reinterpret_cast<float4*>(out + (size_t)(row0 + r) * M + col) = res.f;
            }
        } else {
            for (int r = 0; r < nrows; r++) {
                const float4* uj = reinterpret_cast<const float4*>(sU[r]);
                unsigned long long alo, ahi;
                {
                    F4U u; u.f = uj[0];
                    alo = mul2(u.u.lo, vA[0]);  ahi = mul2(u.u.lo, vB[0]);
                    alo = fma2(u.u.hi, vA[1], alo); ahi = fma2(u.u.hi, vB[1], ahi);
                }
#pragma unroll
                for (int j = 1; j < 5; j++) {
                    F4U u; u.f = uj[j];
                    alo = fma2(u.u.lo, vA[2*j],   alo); ahi = fma2(u.u.lo, vB[2*j],   ahi);
                    alo = fma2(u.u.hi, vA[2*j+1], alo); ahi = fma2(u.u.hi, vB[2*j+1], ahi);
                }
                {
                    F4U u; u.f = uj[5];
                    alo = fma2(u.u.lo, vA[10], alo); ahi = fma2(u.u.lo, vB[10], ahi);
                }
                F4U res; res.u.lo = alo; res.u.hi = ahi;
                *reinterpret_cast<float4*>(out + (size_t)(row0 + r) * M + col) = res.f;
            }
        }
    } else if (col < M) {
        // scalar tail path
        int ncols = M - col; if (ncols > 4) ncols = 4;
        for (int cc = 0; cc < ncols; cc++) {
            const float* p = targ + (size_t)(col + cc) * 5;
            compute_V(p[0], p[1], p[2], p[3], p[4], vs);
            for (int r = 0; r < nrows; r++) {
                float acc = sU[r][0].x * vs[0];
#pragma unroll
                for (int k = 1; k < 11; k++) acc = fmaf(sU[r][k].x, vs[k], acc);
                out[(size_t)(row0 + r) * M + col + cc] = acc;
            }
        }
    }
}

extern "C" void kernel_launch(void* const* d_in, const int* in_sizes, int n_in,
                              void* d_out, int out_size) {
    const float* pred = (const float*)d_in[0];
    const float* targ = (const float*)d_in[1];
    float* out = (float*)d_out;
    int N = in_sizes[0] / 5;
    int M = in_sizes[1] / 5;

    dim3 grid((M + KLD_THREADS * 4 - 1) / (KLD_THREADS * 4),
              (N + KLD_ROWS - 1) / KLD_ROWS);
    kld_fused<<<grid, KLD_THREADS>>>(pred, targ, out, N, M);
}

// round 4
// speedup vs baseline: 1.4552x; 1.1505x over previous
#include <cuda_runtime.h>
#include <math.h>

// ---------------- packed f32x2 helpers (PTX-only; ptxas won't auto-fuse) ----
__device__ __forceinline__ unsigned long long fma2(unsigned long long a,
                                                   unsigned long long b,
                                                   unsigned long long c) {
    unsigned long long d;
    asm("fma.rn.f32x2 %0, %1, %2, %3;" : "=l"(d) : "l"(a), "l"(b), "l"(c));
    return d;
}
__device__ __forceinline__ unsigned long long mul2(unsigned long long a,
                                                   unsigned long long b) {
    unsigned long long d;
    asm("mul.rn.f32x2 %0, %1, %2;" : "=l"(d) : "l"(a), "l"(b));
    return d;
}
__device__ __forceinline__ unsigned long long pk2(float lo, float hi) {
    unsigned long long r;
    asm("mov.b64 %0, {%1, %2};" : "=l"(r) : "f"(lo), "f"(hi));
    return r;
}
union F4U { float4 f; struct { unsigned long long lo, hi; } u; };

// ---------------- per-row U features (fast intrinsics; barrier-critical) ----
__device__ __forceinline__ void compute_U(const float* __restrict__ p,
                                          float2* __restrict__ Urow) {
    const float LOG_TWO_PI = 1.8378770664093454836f;
    const float TWO_PI = 6.2831853071795864769f;
    const float EIGHT_PI = 25.132741228718345908f;
    const float EPS = 1e-6f;

    float eta = p[0], alpha = p[1], psi = p[2];
    float kappa = p[3], beta = p[4];
    float sa, ca, se, ce, sp, cp;
    __sincosf(alpha, &sa, &ca);
    __sincosf(eta,   &se, &ce);
    __sincosf(psi,   &sp, &cp);
    float g1[3] = { ca,       sa * ce,                  sa * se };
    float g2[3] = { -cp * sa, cp * ca * ce - sp * se,   cp * ca * se + sp * ce };
    float g3[3] = { sp * sa,  -sp * ca * ce - cp * se,  -sp * ca * se + cp * ce };

    float km = kappa - 2.f * beta, kp = kappa + 2.f * beta;
    float lkm = __logf(km), lkp = __logf(kp);

    float c  = LOG_TWO_PI + kappa - 0.5f * __logf(km * kp + EPS);
    float ck = __logf(-TWO_PI * (4.f * beta * beta + kappa - kappa * kappa)) + kappa
             - (1.5f * lkm + 1.5f * lkp + EPS);
    float k2 = kappa * kappa, b2 = beta * beta;
    float poly = k2 * k2 - 2.f * kappa * k2 + (2.f - 8.f * b2) * k2
               + 8.f * b2 * kappa + 16.f * b2 * b2 + 4.f * b2;
    float ckk = __logf(TWO_PI * poly) + kappa - (2.5f * lkm + 2.5f * lkp + EPS);
    float cbeta = __logf(EIGHT_PI * kappa) + __logf(beta)
                - (1.5f * lkm + 1.5f * lkp + EPS);

    float l1  = __expf(ck  - c);
    float ekk = __expf(ckk - c);
    float eb  = __expf(cbeta - c);
    float l2 = 0.5f * (1.f - ekk + eb);
    float l3 = 0.5f * (1.f - ekk - eb);

    float E00 = l1*g1[0]*g1[0] + l2*g2[0]*g2[0] + l3*g3[0]*g3[0];
    float E11 = l1*g1[1]*g1[1] + l2*g2[1]*g2[1] + l3*g3[1]*g3[1];
    float E22 = l1*g1[2]*g1[2] + l2*g2[2]*g2[2] + l3*g3[2]*g3[2];
    float E01 = l1*g1[0]*g1[1] + l2*g2[0]*g2[1] + l3*g3[0]*g3[1];
    float E02 = l1*g1[0]*g1[2] + l2*g2[0]*g2[2] + l3*g3[0]*g3[2];
    float E12 = l1*g1[1]*g1[2] + l2*g2[1]*g2[2] + l3*g3[1]*g3[2];

    float Ex0 = l1 * g1[0], Ex1 = l1 * g1[1], Ex2 = l1 * g1[2];

    float qa2 = E00*g2[0]*g2[0] + E11*g2[1]*g2[1] + E22*g2[2]*g2[2]
              + 2.f*(E01*g2[0]*g2[1] + E02*g2[0]*g2[2] + E12*g2[1]*g2[2]);
    float qa3 = E00*g3[0]*g3[0] + E11*g3[1]*g3[1] + E22*g3[2]*g3[2]
              + 2.f*(E01*g3[0]*g3[1] + E02*g3[0]*g3[2] + E12*g3[1]*g3[2]);

    float kdot = kappa * (g1[0]*Ex0 + g1[1]*Ex1 + g1[2]*Ex2);
    float S = -c + kdot + beta * (qa2 - qa3);

    float u[11] = { S, 1.f, Ex0, Ex1, Ex2, E00, E11, E22,
                    2.f*E01, 2.f*E02, 2.f*E12 };
#pragma unroll
    for (int k = 0; k < 11; k++) Urow[k] = make_float2(u[k], u[k]);
    Urow[11] = make_float2(0.f, 0.f);
}

// ---------------- per-col V features (fast intrinsics) ----------------------
__device__ __forceinline__ void compute_V(float eta, float alpha, float psi,
                                          float kappa, float beta,
                                          float v[11]) {
    const float LOG_TWO_PI = 1.8378770664093454836f;
    const float EPS = 1e-6f;
    float sa, ca, se, ce, sp, cp;
    __sincosf(alpha, &sa, &ca);
    __sincosf(eta,   &se, &ce);
    __sincosf(psi,   &sp, &cp);
    float g1x = ca,       g1y = sa * ce,                 g1z = sa * se;
    float g2x = -cp * sa, g2y = cp * ca * ce - sp * se,  g2z = cp * ca * se + sp * ce;
    float g3x = sp * sa,  g3y = -sp * ca * ce - cp * se, g3z = -sp * ca * se + cp * ce;

    float km = kappa - 2.f * beta, kp = kappa + 2.f * beta;
    float cb = LOG_TWO_PI + kappa - 0.5f * __logf(km * kp + EPS);

    v[0] = 1.f;
    v[1] = cb;
    v[2] = -kappa * g1x;
    v[3] = -kappa * g1y;
    v[4] = -kappa * g1z;
    v[5] = beta * (g3x*g3x - g2x*g2x);
    v[6] = beta * (g3y*g3y - g2y*g2y);
    v[7] = beta * (g3z*g3z - g2z*g2z);
    v[8] = beta * (g3x*g3y - g2x*g2y);
    v[9] = beta * (g3x*g3z - g2x*g2z);
    v[10] = beta * (g3y*g3z - g2y*g2z);
}

// ---------------- fused kernel ----------------------------------------------
#define KLD_THREADS 128
#define KLD_ROWS    8

__global__ void __launch_bounds__(KLD_THREADS, 8)
kld_fused(const float* __restrict__ pred, const float* __restrict__ targ,
          float* __restrict__ out, int N, int M) {
    int tid  = threadIdx.x;
    int col  = (blockIdx.x * KLD_THREADS + tid) * 4;
    int row0 = blockIdx.y * KLD_ROWS;
    int nrows = N - row0;
    if (nrows > KLD_ROWS) nrows = KLD_ROWS;

    __shared__ float2 sU[KLD_ROWS][12];

    // --- U: threads 0..nrows-1 compute one row each (fast-intrinsic path) ---
    if (tid < nrows)
        compute_U(pred + (size_t)(row0 + tid) * 5, sU[tid]);

    // --- V: each thread, 4 cols from raw targ params -------------------------
    bool vec = ((M & 3) == 0) && (col + 4 <= M);
    unsigned long long vA[11], vB[11];   // cols {0,1} and {2,3} packed

    if (vec) {
        float tp[20];
        const float4* src = reinterpret_cast<const float4*>(targ + (size_t)col * 5);
#pragma unroll
        for (int q = 0; q < 5; q++)
            *reinterpret_cast<float4*>(&tp[q * 4]) = src[q];

        float v0[11], v1[11];
        compute_V(tp[0],  tp[1],  tp[2],  tp[3],  tp[4],  v0);
        compute_V(tp[5],  tp[6],  tp[7],  tp[8],  tp[9],  v1);
#pragma unroll
        for (int k = 0; k < 11; k++) vA[k] = pk2(v0[k], v1[k]);
        compute_V(tp[10], tp[11], tp[12], tp[13], tp[14], v0);
        compute_V(tp[15], tp[16], tp[17], tp[18], tp[19], v1);
#pragma unroll
        for (int k = 0; k < 11; k++) vB[k] = pk2(v0[k], v1[k]);
    }

    __syncthreads();

    if (vec) {
        if (nrows == KLD_ROWS) {
#pragma unroll
            for (int r = 0; r < KLD_ROWS; r++) {
                const float4* uj = reinterpret_cast<const float4*>(sU[r]);
                unsigned long long alo, ahi;
                {
                    F4U u; u.f = uj[0];                     // {u0,u0,u1,u1}
                    alo = mul2(u.u.lo, vA[0]);  ahi = mul2(u.u.lo, vB[0]);
                    alo = fma2(u.u.hi, vA[1], alo); ahi = fma2(u.u.hi, vB[1], ahi);
                }
#pragma unroll
                for (int j = 1; j < 5; j++) {
                    F4U u; u.f = uj[j];                     // {u2j,u2j,u2j+1,u2j+1}
                    alo = fma2(u.u.lo, vA[2*j],   alo); ahi = fma2(u.u.lo, vB[2*j],   ahi);
                    alo = fma2(u.u.hi, vA[2*j+1], alo); ahi = fma2(u.u.hi, vB[2*j+1], ahi);
                }
                {
                    F4U u; u.f = uj[5];                     // {u10,u10,pad,pad}
                    alo = fma2(u.u.lo, vA[10], alo); ahi = fma2(u.u.lo, vB[10], ahi);
                }
                F4U res; res.u.lo = alo; res.u.hi = ahi;
                *reinterpret_cast<float4*>(out + (size_t)(row0 + r) * M + col) = res.f;
            }
        } else {
            for (int r = 0; r < nrows; r++) {
                const float4* uj = reinterpret_cast<const float4*>(sU[r]);
                unsigned long long alo, ahi;
                {
                    F4U u; u.f = uj[0];
                    alo = mul2(u.u.lo, vA[0]);  ahi = mul2(u.u.lo, vB[0]);
                    alo = fma2(u.u.hi, vA[1], alo); ahi = fma2(u.u.hi, vB[1], ahi);
                }
#pragma unroll
                for (int j = 1; j < 5; j++) {
                    F4U u; u.f = uj[j];
                    alo = fma2(u.u.lo, vA[2*j],   alo); ahi = fma2(u.u.lo, vB[2*j],   ahi);
                    alo = fma2(u.u.hi, vA[2*j+1], alo); ahi = fma2(u.u.hi, vB[2*j+1], ahi);
                }
                {
                    F4U u; u.f = uj[5];
                    alo = fma2(u.u.lo, vA[10], alo); ahi = fma2(u.u.lo, vB[10], ahi);
                }
                F4U res; res.u.lo = alo; res.u.hi = ahi;
                *reinterpret_cast<float4*>(out + (size_t)(row0 + r) * M + col) = res.f;
            }
        }
    } else if (col < M) {
        // scalar tail path
        float vs[11];
        int ncols = M - col; if (ncols > 4) ncols = 4;
        for (int cc = 0; cc < ncols; cc++) {
            const float* p = targ + (size_t)(col + cc) * 5;
            compute_V(p[0], p[1], p[2], p[3], p[4], vs);
            for (int r = 0; r < nrows; r++) {
                float acc = sU[r][0].x * vs[0];
#pragma unroll
                for (int k = 1; k < 11; k++) acc = fmaf(sU[r][k].x, vs[k], acc);
                out[(size_t)(row0 + r) * M + col + cc] = acc;
            }
        }
    }
}

extern "C" void kernel_launch(void* const* d_in, const int* in_sizes, int n_in,
                              void* d_out, int out_size) {
    const float* pred = (const float*)d_in[0];
    const float* targ = (const float*)d_in[1];
    float* out = (float*)d_out;
    int N = in_sizes[0] / 5;
    int M = in_sizes[1] / 5;

    dim3 grid((M + KLD_THREADS * 4 - 1) / (KLD_THREADS * 4),
              (N + KLD_ROWS - 1) / KLD_ROWS);
    kld_fused<<<grid, KLD_THREADS>>>(pred, targ, out, N, M);
}